// round 11
// baseline (speedup 1.0000x reference)
#include <cuda_runtime.h>

// NeighborList: all i<j pairs, minimum-image PBC, cutoff mask.
// Output (float32): [0,P) pair_i | [P,2P) pair_j | [2P,5P) deltas[P,3] | [5P,6P) dist

#define MAXN     8192
#define TPB      256
#define KITER    4
#define BLKPAIRS (TPB * KITER)

__device__ float g_x[MAXN], g_y[MAXN], g_z[MAXN];
__device__ float g_inv[9];
__device__ float g_cellm[9];
__device__ float g_diag[6];   // {inv00,inv11,inv22, cell00,cell11,cell22}; zeros if no PBC
__device__ int   g_general;   // 1 = non-diagonal cell (rare path)

// Fused prep: thread (0,0) inverts/classifies the cell; all threads transpose xyz -> SoA.
__global__ void prep_kernel(const float* __restrict__ xyz,
                            const float* __restrict__ cell, int n) {
    const int k = blockIdx.x * blockDim.x + threadIdx.x;
    if (k < n) {
        g_x[k] = xyz[3 * k + 0];
        g_y[k] = xyz[3 * k + 1];
        g_z[k] = xyz[3 * k + 2];
    }
    if (blockIdx.x == 0 && threadIdx.x == 0) {
        bool zero = true;
        float c[9];
#pragma unroll
        for (int q = 0; q < 9; q++) {
            c[q] = cell[q];
            if (c[q] != 0.0f) zero = false;
        }
        if (zero) {
            c[0] = c[4] = c[8] = 1.0f;
            c[1] = c[2] = c[3] = c[5] = c[6] = c[7] = 0.0f;
        }
#pragma unroll
        for (int q = 0; q < 9; q++) g_cellm[q] = c[q];

        float a = c[0], b = c[1], cc = c[2];
        float d = c[3], e = c[4], f  = c[5];
        float g = c[6], h = c[7], i  = c[8];
        float A =  (e * i - f * h);
        float B = -(d * i - f * g);
        float C =  (d * h - e * g);
        float det = a * A + b * B + cc * C;
        float invdet = 1.0f / det;
        g_inv[0] = A * invdet;
        g_inv[1] = -(b * i - cc * h) * invdet;
        g_inv[2] =  (b * f - cc * e) * invdet;
        g_inv[3] = B * invdet;
        g_inv[4] =  (a * i - cc * g) * invdet;
        g_inv[5] = -(a * f - cc * d) * invdet;
        g_inv[6] = C * invdet;
        g_inv[7] = -(a * h - b * g) * invdet;
        g_inv[8] =  (a * e - b * d) * invdet;

        const bool diag = (c[1] == 0.0f) && (c[2] == 0.0f) && (c[3] == 0.0f) &&
                          (c[5] == 0.0f) && (c[6] == 0.0f) && (c[7] == 0.0f);
        if (zero) {
            g_diag[0] = g_diag[1] = g_diag[2] = 0.0f;   // wrap becomes exact no-op
            g_diag[3] = g_diag[4] = g_diag[5] = 0.0f;
        } else {
            g_diag[0] = g_inv[0]; g_diag[1] = g_inv[4]; g_diag[2] = g_inv[8];
            g_diag[3] = c[0];     g_diag[4] = c[4];     g_diag[5] = c[8];
        }
        g_general = (!zero && !diag) ? 1 : 0;
    }
}

__device__ __forceinline__ float fast_sqrt(float x) {
    float r;
    asm("sqrt.approx.f32 %0, %1;" : "=f"(r) : "f"(x));
    return r;
}

// Row-block mapping: blockIdx.y = row i; block covers BLKPAIRS consecutive j's.
// Loads and plane stores are lane-consecutive. Delta stores use a warp-shuffle
// transpose so each STG is lane-consecutive too (9 wf -> ~3-4 wf per warp-iter).
__global__ void __launch_bounds__(TPB)
nl_kernel(float* __restrict__ out, int n, unsigned P) {
    const int i     = blockIdx.y;
    const int len   = n - 1 - i;                 // pairs in this row
    const int start = blockIdx.x * BLKPAIRS;     // offset within row
    if (start >= len) return;                    // empty block: fast exit

    const bool full = (start + BLKPAIRS) <= len; // uniform: interior block

    const unsigned T    = 2u * (unsigned)n - 1u;
    const unsigned offi = ((unsigned)i * (T - (unsigned)i)) >> 1;

    const int tid  = threadIdx.x;
    const int wid  = tid >> 5;
    const int lane = tid & 31;

    const int general = g_general;
    const float d0 = g_diag[0], d4 = g_diag[1], d8 = g_diag[2];
    const float e0 = g_diag[3], e4 = g_diag[4], e8 = g_diag[5];

    const float xi = g_x[i], yi = g_y[i], zi = g_z[i];   // uniform broadcast

#pragma unroll
    for (int k = 0; k < KITER; k++) {
        const int base_k = start + k * TPB;      // block-uniform
        if (!full && base_k >= len) break;       // uniform exit for tail

        const int jo = base_k + tid;             // pair offset within row
        const bool valid = full || (jo < len);
        const int j = i + 1 + jo;                // j < MAXN always -> safe load

        float dx = xi - g_x[j];
        float dy = yi - g_y[j];
        float dz = zi - g_z[j];

        if (!general) {
            // diagonal (or no) PBC: per-axis wrap; zeros => exact no-op
            dx -= rintf(dx * d0) * e0;           // jnp.round = half-to-even = rintf
            dy -= rintf(dy * d4) * e4;
            dz -= rintf(dz * d8) * e8;
        } else {
            volatile const float* vi9 = g_inv;
            volatile const float* vc9 = g_cellm;
            const float f0 = dx * vi9[0] + dy * vi9[3] + dz * vi9[6];
            const float f1 = dx * vi9[1] + dy * vi9[4] + dz * vi9[7];
            const float f2 = dx * vi9[2] + dy * vi9[5] + dz * vi9[8];
            const float r0 = rintf(f0);
            const float r1 = rintf(f1);
            const float r2 = rintf(f2);
            dx -= r0 * vc9[0] + r1 * vc9[3] + r2 * vc9[6];
            dy -= r0 * vc9[1] + r1 * vc9[4] + r2 * vc9[7];
            dz -= r0 * vc9[2] + r1 * vc9[5] + r2 * vc9[8];
        }

        const float dist = fast_sqrt(dx * dx + dy * dy + dz * dz);
        const bool m = (dist <= 5.0f);

        const size_t p = (size_t)offi + (size_t)jo;
        if (valid) {
            out[p]                 = m ? (float)i : -1.0f;
            out[P + p]             = m ? (float)j : -1.0f;
            out[5 * (size_t)P + p] = m ? dist : 0.0f;
        }

        // masked deltas for this lane's pair
        const float mdx = m ? dx : 0.0f;
        const float mdy = m ? dy : 0.0f;
        const float mdz = m ? dz : 0.0f;

        // warp-shuffle transpose: warp owns 96 consecutive floats at 3*wb
        const int wb_jo = base_k + 32 * wid;                 // lane0's pair offset
        const size_t wb = (size_t)offi + (size_t)wb_jo;
        float* db = out + 2 * (size_t)P + 3 * wb;
        const int vcount = full ? 32 : (len - wb_jo);        // may be <=0 or >32-capped below

#pragma unroll
        for (int c = 0; c < 3; c++) {
            const int q  = 32 * c + lane;   // position within the 96-float region
            const int sl = q / 3;           // source lane (owns pair wb+sl)
            const int cp = q - 3 * sl;      // component 0/1/2
            const float vx = __shfl_sync(0xffffffffu, mdx, sl);
            const float vy = __shfl_sync(0xffffffffu, mdy, sl);
            const float vz = __shfl_sync(0xffffffffu, mdz, sl);
            const float val = (cp == 0) ? vx : ((cp == 1) ? vy : vz);
            if (full || q < 3 * vcount) db[q] = val;
        }
    }
}

extern "C" void kernel_launch(void* const* d_in, const int* in_sizes, int n_in,
                              void* d_out, int out_size) {
    const float* xyz  = (const float*)d_in[0];
    const float* cell = (const float*)d_in[1];
    if (n_in >= 2 && in_sizes[0] == 9 && in_sizes[1] != 9) {
        const float* t = xyz; xyz = cell; cell = t;
    }
    const int n = (in_sizes[0] == 9 && n_in >= 2) ? in_sizes[1] / 3 : in_sizes[0] / 3;
    const unsigned P = (unsigned)((size_t)n * (size_t)(n - 1) / 2);

    prep_kernel<<<(n + TPB - 1) / TPB, TPB>>>(xyz, cell, n);

    const int maxlen = n - 1;
    dim3 grid((maxlen + BLKPAIRS - 1) / BLKPAIRS, n - 1);
    nl_kernel<<<grid, TPB>>>((float*)d_out, n, P);
}

// round 12
// speedup vs baseline: 1.1059x; 1.1059x over previous
#include <cuda_runtime.h>

// NeighborList: all i<j pairs, minimum-image PBC, cutoff mask.
// Output (float32): [0,P) pair_i | [P,2P) pair_j | [2P,5P) deltas[P,3] | [5P,6P) dist

#define MAXN     8192
#define TPB      256
#define KITER    4
#define BLKPAIRS (TPB * KITER)

__device__ float g_x[MAXN], g_y[MAXN], g_z[MAXN];
__device__ float g_inv[9];
__device__ float g_cellm[9];
__device__ float g_diag[6];   // {inv00,inv11,inv22, cell00,cell11,cell22}; zeros if no PBC
__device__ int   g_general;   // 1 = non-diagonal cell (rare path)

// Fused prep: thread (0,0) inverts/classifies the cell; all threads transpose xyz -> SoA.
__global__ void prep_kernel(const float* __restrict__ xyz,
                            const float* __restrict__ cell, int n) {
    const int k = blockIdx.x * blockDim.x + threadIdx.x;
    if (k < n) {
        g_x[k] = xyz[3 * k + 0];
        g_y[k] = xyz[3 * k + 1];
        g_z[k] = xyz[3 * k + 2];
    }
    if (blockIdx.x == 0 && threadIdx.x == 0) {
        bool zero = true;
        float c[9];
#pragma unroll
        for (int q = 0; q < 9; q++) {
            c[q] = cell[q];
            if (c[q] != 0.0f) zero = false;
        }
        if (zero) {
            c[0] = c[4] = c[8] = 1.0f;
            c[1] = c[2] = c[3] = c[5] = c[6] = c[7] = 0.0f;
        }
#pragma unroll
        for (int q = 0; q < 9; q++) g_cellm[q] = c[q];

        float a = c[0], b = c[1], cc = c[2];
        float d = c[3], e = c[4], f  = c[5];
        float g = c[6], h = c[7], i  = c[8];
        float A =  (e * i - f * h);
        float B = -(d * i - f * g);
        float C =  (d * h - e * g);
        float det = a * A + b * B + cc * C;
        float invdet = 1.0f / det;
        g_inv[0] = A * invdet;
        g_inv[1] = -(b * i - cc * h) * invdet;
        g_inv[2] =  (b * f - cc * e) * invdet;
        g_inv[3] = B * invdet;
        g_inv[4] =  (a * i - cc * g) * invdet;
        g_inv[5] = -(a * f - cc * d) * invdet;
        g_inv[6] = C * invdet;
        g_inv[7] = -(a * h - b * g) * invdet;
        g_inv[8] =  (a * e - b * d) * invdet;

        const bool diag = (c[1] == 0.0f) && (c[2] == 0.0f) && (c[3] == 0.0f) &&
                          (c[5] == 0.0f) && (c[6] == 0.0f) && (c[7] == 0.0f);
        if (zero) {
            g_diag[0] = g_diag[1] = g_diag[2] = 0.0f;   // wrap becomes exact no-op
            g_diag[3] = g_diag[4] = g_diag[5] = 0.0f;
        } else {
            g_diag[0] = g_inv[0]; g_diag[1] = g_inv[4]; g_diag[2] = g_inv[8];
            g_diag[3] = c[0];     g_diag[4] = c[4];     g_diag[5] = c[8];
        }
        g_general = (!zero && !diag) ? 1 : 0;
    }
}

__device__ __forceinline__ float fast_sqrt(float x) {
    float r;
    asm("sqrt.approx.f32 %0, %1;" : "=f"(r) : "f"(x));
    return r;
}

// Mirrored-row packing: blockIdx.y = y pairs row i1=y with row i2=n-2-y.
// Combined pair count = (n-1-y) + (y+1) = n  -> exactly n/BLKPAIRS full blocks
// in x, zero wasted threads, no bounds checks. Middle row (y = i2) is covered
// twice with identical writes (deterministic, harmless).
__global__ void __launch_bounds__(TPB)
nl_kernel(float* __restrict__ out, int n, unsigned P) {
    const int y    = blockIdx.y;
    const int i1   = y;
    const int i2   = n - 2 - y;
    const int len1 = n - 1 - i1;          // pairs in row i1; row i2 has n-len1
    const int tid  = threadIdx.x;
    const int start = blockIdx.x * BLKPAIRS;

    const unsigned T    = 2u * (unsigned)n - 1u;
    const unsigned off1 = ((unsigned)i1 * (T - (unsigned)i1)) >> 1;
    const unsigned off2 = ((unsigned)i2 * (T - (unsigned)i2)) >> 1;

    const int general = g_general;
    const float d0 = g_diag[0], d4 = g_diag[1], d8 = g_diag[2];
    const float e0 = g_diag[3], e4 = g_diag[4], e8 = g_diag[5];

    // both rows' coordinates (uniform broadcasts)
    const float ax1 = g_x[i1], ay1 = g_y[i1], az1 = g_z[i1];
    const float ax2 = g_x[i2], ay2 = g_y[i2], az2 = g_z[i2];

#pragma unroll
    for (int k = 0; k < KITER; k++) {
        const int c = start + k * TPB + tid;       // combined index in [0, n)
        if (c >= n) break;                          // only for n % BLKPAIRS != 0

        const bool s2 = (c >= len1);                // segment select
        const int  jo = s2 ? (c - len1) : c;        // offset within selected row
        const int  i  = s2 ? i2 : i1;
        const unsigned offi = s2 ? off2 : off1;
        const int  j  = i + 1 + jo;                 // j < MAXN always -> safe load

        const float xi = s2 ? ax2 : ax1;
        const float yi = s2 ? ay2 : ay1;
        const float zi = s2 ? az2 : az1;

        float dx = xi - g_x[j];
        float dy = yi - g_y[j];
        float dz = zi - g_z[j];

        if (!general) {
            // diagonal (or no) PBC: per-axis wrap; zeros => exact no-op
            dx -= rintf(dx * d0) * e0;              // jnp.round = half-to-even = rintf
            dy -= rintf(dy * d4) * e4;
            dz -= rintf(dz * d8) * e8;
        } else {
            volatile const float* vi9 = g_inv;
            volatile const float* vc9 = g_cellm;
            const float f0 = dx * vi9[0] + dy * vi9[3] + dz * vi9[6];
            const float f1 = dx * vi9[1] + dy * vi9[4] + dz * vi9[7];
            const float f2 = dx * vi9[2] + dy * vi9[5] + dz * vi9[8];
            const float r0 = rintf(f0);
            const float r1 = rintf(f1);
            const float r2 = rintf(f2);
            dx -= r0 * vc9[0] + r1 * vc9[3] + r2 * vc9[6];
            dy -= r0 * vc9[1] + r1 * vc9[4] + r2 * vc9[7];
            dz -= r0 * vc9[2] + r1 * vc9[5] + r2 * vc9[8];
        }

        const float dist = fast_sqrt(dx * dx + dy * dy + dz * dz);
        const bool m = (dist <= 5.0f);

        const size_t p = (size_t)offi + (size_t)jo;
        out[p]                 = m ? (float)i : -1.0f;
        out[P + p]             = m ? (float)j : -1.0f;
        out[5 * (size_t)P + p] = m ? dist : 0.0f;
        float* db = out + 2 * (size_t)P + 3 * p;    // lane-consecutive scalar stores
        db[0] = m ? dx : 0.0f;
        db[1] = m ? dy : 0.0f;
        db[2] = m ? dz : 0.0f;
    }
}

extern "C" void kernel_launch(void* const* d_in, const int* in_sizes, int n_in,
                              void* d_out, int out_size) {
    const float* xyz  = (const float*)d_in[0];
    const float* cell = (const float*)d_in[1];
    if (n_in >= 2 && in_sizes[0] == 9 && in_sizes[1] != 9) {
        const float* t = xyz; xyz = cell; cell = t;
    }
    const int n = (in_sizes[0] == 9 && n_in >= 2) ? in_sizes[1] / 3 : in_sizes[0] / 3;
    const unsigned P = (unsigned)((size_t)n * (size_t)(n - 1) / 2);

    prep_kernel<<<(n + TPB - 1) / TPB, TPB>>>(xyz, cell, n);

    dim3 grid((n + BLKPAIRS - 1) / BLKPAIRS, (unsigned)(n / 2));  // y pairs (y, n-2-y)
    nl_kernel<<<grid, TPB>>>((float*)d_out, n, P);
}

// round 13
// speedup vs baseline: 1.1321x; 1.0237x over previous
#include <cuda_runtime.h>

// NeighborList: all i<j pairs, minimum-image PBC, cutoff mask.
// Output (float32): [0,P) pair_i | [P,2P) pair_j | [2P,5P) deltas[P,3] | [5P,6P) dist

#define MAXN     8192
#define TPB      256
#define KITER    4
#define BLKPAIRS (TPB * KITER)

__device__ float g_x[MAXN], g_y[MAXN], g_z[MAXN];
__device__ float g_inv[9];
__device__ float g_cellm[9];
__device__ float g_diag[6];   // {inv00,inv11,inv22, cell00,cell11,cell22}; zeros if no PBC
__device__ int   g_general;   // 1 = non-diagonal cell (rare path)

// Fused prep: thread (0,0) inverts/classifies the cell; all threads transpose xyz -> SoA.
__global__ void prep_kernel(const float* __restrict__ xyz,
                            const float* __restrict__ cell, int n) {
    const int k = blockIdx.x * blockDim.x + threadIdx.x;
    if (k < n) {
        g_x[k] = xyz[3 * k + 0];
        g_y[k] = xyz[3 * k + 1];
        g_z[k] = xyz[3 * k + 2];
    }
    if (blockIdx.x == 0 && threadIdx.x == 0) {
        bool zero = true;
        float c[9];
#pragma unroll
        for (int q = 0; q < 9; q++) {
            c[q] = cell[q];
            if (c[q] != 0.0f) zero = false;
        }
        if (zero) {
            c[0] = c[4] = c[8] = 1.0f;
            c[1] = c[2] = c[3] = c[5] = c[6] = c[7] = 0.0f;
        }
#pragma unroll
        for (int q = 0; q < 9; q++) g_cellm[q] = c[q];

        float a = c[0], b = c[1], cc = c[2];
        float d = c[3], e = c[4], f  = c[5];
        float g = c[6], h = c[7], i  = c[8];
        float A =  (e * i - f * h);
        float B = -(d * i - f * g);
        float C =  (d * h - e * g);
        float det = a * A + b * B + cc * C;
        float invdet = 1.0f / det;
        g_inv[0] = A * invdet;
        g_inv[1] = -(b * i - cc * h) * invdet;
        g_inv[2] =  (b * f - cc * e) * invdet;
        g_inv[3] = B * invdet;
        g_inv[4] =  (a * i - cc * g) * invdet;
        g_inv[5] = -(a * f - cc * d) * invdet;
        g_inv[6] = C * invdet;
        g_inv[7] = -(a * h - b * g) * invdet;
        g_inv[8] =  (a * e - b * d) * invdet;

        const bool diag = (c[1] == 0.0f) && (c[2] == 0.0f) && (c[3] == 0.0f) &&
                          (c[5] == 0.0f) && (c[6] == 0.0f) && (c[7] == 0.0f);
        if (zero) {
            g_diag[0] = g_diag[1] = g_diag[2] = 0.0f;   // wrap becomes exact no-op
            g_diag[3] = g_diag[4] = g_diag[5] = 0.0f;
        } else {
            g_diag[0] = g_inv[0]; g_diag[1] = g_inv[4]; g_diag[2] = g_inv[8];
            g_diag[3] = c[0];     g_diag[4] = c[4];     g_diag[5] = c[8];
        }
        g_general = (!zero && !diag) ? 1 : 0;
    }
}

__device__ __forceinline__ float fast_sqrt(float x) {
    float r;
    asm("sqrt.approx.f32 %0, %1;" : "=f"(r) : "f"(x));
    return r;
}

// Row-block mapping: blockIdx.y = row i; block covers BLKPAIRS consecutive j's.
// All memory ops lane-consecutive. Store addresses advance by constant strides
// per k-iteration -> pure pointer increments (no per-iter 64-bit address math).
__global__ void __launch_bounds__(TPB)
nl_kernel(float* __restrict__ out, int n, unsigned P) {
    const int i     = blockIdx.y;
    const int len   = n - 1 - i;                 // pairs in this row
    const int start = blockIdx.x * BLKPAIRS;     // offset within row
    if (start >= len) return;                    // empty block: fast exit

    const bool full = (start + BLKPAIRS) <= len; // uniform: interior block

    const unsigned T    = 2u * (unsigned)n - 1u;
    const unsigned offi = ((unsigned)i * (T - (unsigned)i)) >> 1;

    const int tid = threadIdx.x;

    const int general = g_general;
    const float d0 = g_diag[0], d4 = g_diag[1], d8 = g_diag[2];
    const float e0 = g_diag[3], e4 = g_diag[4], e8 = g_diag[5];

    const float xi = g_x[i], yi = g_y[i], zi = g_z[i];   // uniform broadcast
    const float fi = (float)i;                            // hoisted I2F

    int jo = start + tid;                        // pair offset within row
    const size_t p0 = (size_t)offi + (size_t)jo;
    float* pi = out + p0;
    float* pj = out + (size_t)P + p0;
    float* pd = out + 5 * (size_t)P + p0;
    float* db = out + 2 * (size_t)P + 3 * p0;

#pragma unroll
    for (int k = 0; k < KITER; k++) {
        if (!full && jo >= len) break;          // tail block only
        const int j = i + 1 + jo;               // j < MAXN always -> safe load

        float dx = xi - g_x[j];
        float dy = yi - g_y[j];
        float dz = zi - g_z[j];

        if (!general) {
            // diagonal (or no) PBC: per-axis wrap; zeros => exact no-op
            dx -= rintf(dx * d0) * e0;          // jnp.round = half-to-even = rintf
            dy -= rintf(dy * d4) * e4;
            dz -= rintf(dz * d8) * e8;
        } else {
            volatile const float* vi9 = g_inv;
            volatile const float* vc9 = g_cellm;
            const float f0 = dx * vi9[0] + dy * vi9[3] + dz * vi9[6];
            const float f1 = dx * vi9[1] + dy * vi9[4] + dz * vi9[7];
            const float f2 = dx * vi9[2] + dy * vi9[5] + dz * vi9[8];
            const float r0 = rintf(f0);
            const float r1 = rintf(f1);
            const float r2 = rintf(f2);
            dx -= r0 * vc9[0] + r1 * vc9[3] + r2 * vc9[6];
            dy -= r0 * vc9[1] + r1 * vc9[4] + r2 * vc9[7];
            dz -= r0 * vc9[2] + r1 * vc9[5] + r2 * vc9[8];
        }

        const float dist = fast_sqrt(dx * dx + dy * dy + dz * dz);
        const bool m = (dist <= 5.0f);

        *pi = m ? fi : -1.0f;
        *pj = m ? (float)j : -1.0f;
        *pd = m ? dist : 0.0f;
        db[0] = m ? dx : 0.0f;                  // lane-consecutive scalar stores
        db[1] = m ? dy : 0.0f;
        db[2] = m ? dz : 0.0f;

        pi += TPB; pj += TPB; pd += TPB; db += 3 * TPB;
        jo += TPB;
    }
}

extern "C" void kernel_launch(void* const* d_in, const int* in_sizes, int n_in,
                              void* d_out, int out_size) {
    const float* xyz  = (const float*)d_in[0];
    const float* cell = (const float*)d_in[1];
    if (n_in >= 2 && in_sizes[0] == 9 && in_sizes[1] != 9) {
        const float* t = xyz; xyz = cell; cell = t;
    }
    const int n = (in_sizes[0] == 9 && n_in >= 2) ? in_sizes[1] / 3 : in_sizes[0] / 3;
    const unsigned P = (unsigned)((size_t)n * (size_t)(n - 1) / 2);

    prep_kernel<<<(n + TPB - 1) / TPB, TPB>>>(xyz, cell, n);

    const int maxlen = n - 1;
    dim3 grid((maxlen + BLKPAIRS - 1) / BLKPAIRS, n - 1);
    nl_kernel<<<grid, TPB>>>((float*)d_out, n, P);
}